// round 16
// baseline (speedup 1.0000x reference)
#include <cuda_runtime.h>
#include <cstdint>

#define B_    32
#define C_    128
#define H_    56
#define W_    56
#define OC_   256
#define HW_   (H_ * W_)          // 3136
#define KDIM  1152               // C*9
#define M_    (B_ * HW_)         // 100352
#define NW_   (OC_ * KDIM)       // 294912

#define HP    58
#define WP    58
#define HWP   (HP * WP)          // 3364

#define BM    128
#define BN    128
#define NSTAGE 36                // 9 taps * 4 channel-chunks of 32
#define NT    256                // 8 warps

// ---- static device scratch ----
// planar split x, padded NHWC: [pixP][cb 4][half 2][32ch] u16; halo = 0 (bss)
__device__ unsigned short g_xhl[(size_t)B_ * HWP * C_ * 2];
// planar split W: [oc][tap 9][cb 4][half 2][32ch] u16
__device__ unsigned short g_whl[(size_t)NW_ * 2];

__device__ __forceinline__ void split_bf16(float f, unsigned& hi, unsigned& lo) {
    unsigned u  = __float_as_uint(f);
    unsigned hu = (u + 0x8000u) & 0xFFFF0000u;
    float fl    = f - __uint_as_float(hu);
    hi = hu >> 16;
    lo = (__float_as_uint(fl) + 0x8000u) >> 16;
}

// merged prep: b < B_ -> transpose+split slice; b == B_ -> W split
__global__ void prep_kernel(const float* __restrict__ x,
                            const float* __restrict__ Wm) {
    const int b  = blockIdx.z;
    const int tx = threadIdx.x, ty = threadIdx.y;   // 32 x 8
    if (b < B_) {
        __shared__ unsigned t[32][33];
        const int h  = blockIdx.y;
        const int cb = (blockIdx.x >> 1) * 32;
        const int wb = (blockIdx.x & 1) * 32;
        const int w  = wb + tx;
        if (w < W_) {
#pragma unroll
            for (int i = 0; i < 4; i++) {
                int c = cb + ty + 8 * i;
                unsigned hi, lo;
                split_bf16(x[(((size_t)b * C_ + c) * H_ + h) * W_ + w], hi, lo);
                t[ty + 8 * i][tx] = (hi << 16) | lo;
            }
        }
        __syncthreads();
#pragma unroll
        for (int i = 0; i < 4; i++) {
            int wo = wb + ty + 8 * i;
            int co = cb + tx;
            if (wo < W_) {
                unsigned v = t[tx][ty + 8 * i];
                size_t pixP = ((size_t)b * HP + h + 1) * WP + wo + 1;
                size_t base = (pixP * 4 + (co >> 5)) * 64 + (co & 31);
                g_xhl[base]      = (unsigned short)(v >> 16);      // hi plane
                g_xhl[base + 32] = (unsigned short)(v & 0xFFFF);   // lo plane
            }
        }
    } else {
        const int tlin   = ty * 32 + tx;
        const int base0  = (blockIdx.y * gridDim.x + blockIdx.x) * 256 + tlin;
        const int stride = gridDim.x * gridDim.y * 256;
        for (int j = base0; j < NW_; j += stride) {
            int oc  = j / KDIM;
            int r   = j - oc * KDIM;
            int c   = r / 9;
            int tap = r - c * 9;
            unsigned hi, lo;
            split_bf16(Wm[j], hi, lo);
            size_t base = ((size_t)(oc * 36 + tap * 4 + (c >> 5))) * 64 + (c & 31);
            g_whl[base]      = (unsigned short)hi;
            g_whl[base + 32] = (unsigned short)lo;
        }
    }
}

// ---- helpers ----
__device__ __forceinline__ unsigned smem_u32(const void* p) {
    return (unsigned)__cvta_generic_to_shared(p);
}
__device__ __forceinline__ void cpa16(unsigned dst, const void* src) {
    asm volatile("cp.async.cg.shared.global [%0], [%1], 16;\n"
                 :: "r"(dst), "l"(src));
}
__device__ __forceinline__ void ldsm4(unsigned* r, unsigned addr) {
    asm volatile("ldmatrix.sync.aligned.m8n8.x4.shared.b16 {%0,%1,%2,%3}, [%4];"
                 : "=r"(r[0]), "=r"(r[1]), "=r"(r[2]), "=r"(r[3]) : "r"(addr));
}
__device__ __forceinline__ void mma16816(float* c, const unsigned* a,
                                         unsigned b0, unsigned b1) {
    asm("mma.sync.aligned.m16n8k16.row.col.f32.bf16.bf16.f32 "
        "{%0,%1,%2,%3}, {%4,%5,%6,%7}, {%8,%9}, {%0,%1,%2,%3};"
        : "+f"(c[0]), "+f"(c[1]), "+f"(c[2]), "+f"(c[3])
        : "r"(a[0]), "r"(a[1]), "r"(a[2]), "r"(a[3]), "r"(b0), "r"(b1));
}

// ---- smem layout (bytes) ----
// four planar tiles, 128 rows x 80B (64B data + 16B pad => conflict-free, no swizzle)
#define SM_BIAS 0
#define SM_TILE 1024
#define T_AH    0
#define T_AL    10240
#define T_BH    20480
#define T_BL    30720
#define STG     40960
#define SMEM_TOTAL (SM_TILE + 2 * STG)   // 82944 -> 2 CTAs/SM

__global__ __launch_bounds__(NT, 2)
void conv_hmma_kernel(const float* __restrict__ bias, float* __restrict__ out) {
    extern __shared__ char smem[];
    const int tid  = threadIdx.x;
    const int lane = tid & 31;
    const int wid  = tid >> 5;
    const int m0   = blockIdx.x * BM;
    const int n0   = blockIdx.y * BN;

    ((float*)(smem + SM_BIAS))[tid] = bias[tid];   // NT == OC_

    // ---- producers: thread = (row 0..127, grp 0..1); grp = 32B piece of each 64B half
    const int rowP = tid & 127;
    const int grp  = tid >> 7;
    const int p    = m0 + rowP;
    const int bimg = p / HW_;
    const int hw   = p - bimg * HW_;
    const int h    = hw / W_;
    const int w    = hw - h * W_;
    const char* agbase = (const char*)g_xhl
                       + (((size_t)bimg * HP + h) * WP + w) * 512 + grp * 32;
    const char* bgbase = (const char*)g_whl + (size_t)(n0 + rowP) * 4608 + grp * 32;
    const unsigned rdst = (unsigned)(rowP * 80 + grp * 32);

    auto load_stage = [&](int s, int slot) {
        char* stg = smem + SM_TILE + slot * STG;
        int tap = s >> 2;
        int cb  = s & 3;
        int kh  = tap / 3;
        int kw  = tap - 3 * kh;
        const char* asrc = agbase + ((size_t)kh * WP + kw) * 512 + cb * 128;
        const char* bsrc = bgbase + (tap * 4 + cb) * 128;
        unsigned sb = smem_u32(stg);
        cpa16(sb + T_AH + rdst,      asrc);         // hi half
        cpa16(sb + T_AH + rdst + 16, asrc + 16);
        cpa16(sb + T_AL + rdst,      asrc + 64);    // lo half (+64B)
        cpa16(sb + T_AL + rdst + 16, asrc + 80);
        cpa16(sb + T_BH + rdst,      bsrc);
        cpa16(sb + T_BH + rdst + 16, bsrc + 16);
        cpa16(sb + T_BL + rdst,      bsrc + 64);
        cpa16(sb + T_BL + rdst + 16, bsrc + 80);
        asm volatile("cp.async.commit_group;\n");
    };

    // warp tiling: 2 (M) x 4 (N) warps, warp tile 64 x 32
    const int wm = (wid & 1) * 64;
    const int wn = (wid >> 1) * 32;

    float acc[4][4][4];
#pragma unroll
    for (int a = 0; a < 4; a++)
#pragma unroll
        for (int b = 0; b < 4; b++)
#pragma unroll
            for (int cq = 0; cq < 4; cq++) acc[a][b][cq] = 0.0f;

    load_stage(0, 0);

    for (int s = 0; s < NSTAGE; s++) {
        asm volatile("cp.async.wait_group 0;\n");
        __syncthreads();
        if (s + 1 < NSTAGE) load_stage(s + 1, (s + 1) & 1);

        char* stg = smem + SM_TILE + (s & 1) * STG;
        const unsigned ah = smem_u32(stg + T_AH);
        const unsigned al = smem_u32(stg + T_AL);
        const unsigned bh = smem_u32(stg + T_BH);
        const unsigned bl = smem_u32(stg + T_BL);

#pragma unroll
        for (int q = 0; q < 2; q++) {           // two 16-k chunks
            unsigned Ah[4][4], Al[4][4];
#pragma unroll
            for (int mi = 0; mi < 4; mi++) {
                unsigned off = (unsigned)((wm + mi * 16 + (lane & 15)) * 80
                                          + q * 32 + (lane >> 4) * 16);
                ldsm4(Ah[mi], ah + off);
                ldsm4(Al[mi], al + off);
            }
#pragma unroll
            for (int ni = 0; ni < 2; ni++) {
                int g = lane >> 3, r = lane & 7;
                unsigned boff = (unsigned)((wn + ni * 16 + ((g & 2) ? 8 : 0) + r) * 80
                                           + q * 32 + (g & 1) * 16);
                unsigned Bh[4], Bl[4];
                ldsm4(Bh, bh + boff);
                ldsm4(Bl, bl + boff);
                // T1: hi*hi
#pragma unroll
                for (int mi = 0; mi < 4; mi++)
                    mma16816(acc[mi][ni * 2 + 0], Ah[mi], Bh[0], Bh[1]);
#pragma unroll
                for (int mi = 0; mi < 4; mi++)
                    mma16816(acc[mi][ni * 2 + 1], Ah[mi], Bh[2], Bh[3]);
                // T2: lo*hi
#pragma unroll
                for (int mi = 0; mi < 4; mi++)
                    mma16816(acc[mi][ni * 2 + 0], Al[mi], Bh[0], Bh[1]);
#pragma unroll
                for (int mi = 0; mi < 4; mi++)
                    mma16816(acc[mi][ni * 2 + 1], Al[mi], Bh[2], Bh[3]);
                // T3: hi*lo
#pragma unroll
                for (int mi = 0; mi < 4; mi++)
                    mma16816(acc[mi][ni * 2 + 0], Ah[mi], Bl[0], Bl[1]);
#pragma unroll
                for (int mi = 0; mi < 4; mi++)
                    mma16816(acc[mi][ni * 2 + 1], Ah[mi], Bl[2], Bl[3]);
            }
        }
    }

    __syncthreads();

    // ---- epilogue: transpose through smem, coalesced float4 stores ----
    float* Cs = (float*)(smem + SM_TILE);   // [oc 128][pix 128] = 64KB
#pragma unroll
    for (int mi = 0; mi < 4; mi++)
#pragma unroll
        for (int nq = 0; nq < 4; nq++) {
            int r0 = wm + mi * 16 + (lane >> 2);
            int cb = wn + nq * 8 + (lane & 3) * 2;
            Cs[(cb + 0) * BM + r0]     = acc[mi][nq][0];
            Cs[(cb + 1) * BM + r0]     = acc[mi][nq][1];
            Cs[(cb + 0) * BM + r0 + 8] = acc[mi][nq][2];
            Cs[(cb + 1) * BM + r0 + 8] = acc[mi][nq][3];
        }
    __syncthreads();

    const float* bs = (const float*)(smem + SM_BIAS);
    for (int g = tid; g < BN * (BM / 4); g += NT) {
        int ocl  = g >> 5;
        int pixl = (g & 31) * 4;
        int pp   = m0 + pixl;
        int bi   = pp / HW_;
        int off  = pp - bi * HW_;
        int oc   = n0 + ocl;
        float4 v = *(const float4*)&Cs[ocl * BM + pixl];
        float bv = bs[oc];
        v.x += bv; v.y += bv; v.z += bv; v.w += bv;
        *(float4*)(out + (size_t)bi * OC_ * HW_ + (size_t)oc * HW_ + off) = v;
    }
}

extern "C" void kernel_launch(void* const* d_in, const int* in_sizes, int n_in,
                              void* d_out, int out_size) {
    const float* x  = (const float*)d_in[0];
    const float* Wm = (const float*)d_in[1];
    const float* bb = (const float*)d_in[2];
    float* out      = (float*)d_out;

    dim3 pgrid(8, H_, B_ + 1);             // z = B_ slice does W split
    prep_kernel<<<pgrid, dim3(32, 8)>>>(x, Wm);

    cudaFuncSetAttribute(conv_hmma_kernel,
                         cudaFuncAttributeMaxDynamicSharedMemorySize, SMEM_TOTAL);
    dim3 grid(M_ / BM, OC_ / BN);   // 784 x 2
    conv_hmma_kernel<<<grid, NT, SMEM_TOTAL>>>(bb, out);
}

// round 17
// speedup vs baseline: 1.6483x; 1.6483x over previous
#include <cuda_runtime.h>
#include <cstdint>

#define B_    32
#define C_    128
#define H_    56
#define W_    56
#define OC_   256
#define HW_   (H_ * W_)          // 3136
#define KDIM  1152               // C*9
#define M_    (B_ * HW_)         // 100352
#define NW_   (OC_ * KDIM)       // 294912

#define HP    58
#define WP    58
#define HWP   (HP * WP)          // 3364

#define BM    128
#define BN    128
#define NSTAGE 36                // 9 taps * 4 channel-chunks of 32
#define NT    256                // 8 warps

// ---- static device scratch ----
// x, padded NHWC, hi|lo packed per 32-ch block:
//   [pixP][cb 4][hi 32ch u16 | lo 32ch u16]  -> 512B per pixel; halo = 0 (bss)
__device__ unsigned short g_xhl[(size_t)B_ * HWP * C_ * 2];
// W: [oc][tap 9][cb 4][hi 32ch | lo 32ch]    -> 4608B per oc
__device__ unsigned short g_whl[(size_t)NW_ * 2];

__device__ __forceinline__ void split_bf16(float f, unsigned& hi, unsigned& lo) {
    unsigned u  = __float_as_uint(f);
    unsigned hu = (u + 0x8000u) & 0xFFFF0000u;
    float fl    = f - __uint_as_float(hu);
    hi = hu >> 16;
    lo = (__float_as_uint(fl) + 0x8000u) >> 16;
}

// merged prep: b < B_ -> transpose+split slice; b == B_ -> W split
__global__ void prep_kernel(const float* __restrict__ x,
                            const float* __restrict__ Wm) {
    const int b  = blockIdx.z;
    const int tx = threadIdx.x, ty = threadIdx.y;   // 32 x 8
    if (b < B_) {
        __shared__ unsigned t[32][33];
        const int h  = blockIdx.y;
        const int cb = (blockIdx.x >> 1) * 32;
        const int wb = (blockIdx.x & 1) * 32;
        const int w  = wb + tx;
        if (w < W_) {
#pragma unroll
            for (int i = 0; i < 4; i++) {
                int c = cb + ty + 8 * i;
                unsigned hi, lo;
                split_bf16(x[(((size_t)b * C_ + c) * H_ + h) * W_ + w], hi, lo);
                t[ty + 8 * i][tx] = (hi << 16) | lo;
            }
        }
        __syncthreads();
#pragma unroll
        for (int i = 0; i < 4; i++) {
            int wo = wb + ty + 8 * i;
            int co = cb + tx;
            if (wo < W_) {
                unsigned v = t[tx][ty + 8 * i];
                size_t pixP = ((size_t)b * HP + h + 1) * WP + wo + 1;
                size_t base = (pixP * 4 + (co >> 5)) * 64 + (co & 31);
                g_xhl[base]      = (unsigned short)(v >> 16);      // hi half
                g_xhl[base + 32] = (unsigned short)(v & 0xFFFF);   // lo half
            }
        }
    } else {
        const int tlin   = ty * 32 + tx;
        const int base0  = (blockIdx.y * gridDim.x + blockIdx.x) * 256 + tlin;
        const int stride = gridDim.x * gridDim.y * 256;
        for (int j = base0; j < NW_; j += stride) {
            int oc  = j / KDIM;
            int r   = j - oc * KDIM;
            int c   = r / 9;
            int tap = r - c * 9;
            unsigned hi, lo;
            split_bf16(Wm[j], hi, lo);
            size_t base = ((size_t)(oc * 36 + tap * 4 + (c >> 5))) * 64 + (c & 31);
            g_whl[base]      = (unsigned short)hi;
            g_whl[base + 32] = (unsigned short)lo;
        }
    }
}

// ---- helpers ----
__device__ __forceinline__ unsigned smem_u32(const void* p) {
    return (unsigned)__cvta_generic_to_shared(p);
}
__device__ __forceinline__ unsigned sw128(unsigned off) {
    return off ^ ((off >> 3) & 0x70);
}
__device__ __forceinline__ void cpa16(unsigned dst, const void* src) {
    asm volatile("cp.async.cg.shared.global [%0], [%1], 16;\n"
                 :: "r"(dst), "l"(src));
}
__device__ __forceinline__ void ldsm4(unsigned* r, unsigned addr) {
    asm volatile("ldmatrix.sync.aligned.m8n8.x4.shared.b16 {%0,%1,%2,%3}, [%4];"
                 : "=r"(r[0]), "=r"(r[1]), "=r"(r[2]), "=r"(r[3]) : "r"(addr));
}
__device__ __forceinline__ void mma16816(float* c, const unsigned* a,
                                         unsigned b0, unsigned b1) {
    asm("mma.sync.aligned.m16n8k16.row.col.f32.bf16.bf16.f32 "
        "{%0,%1,%2,%3}, {%4,%5,%6,%7}, {%8,%9}, {%0,%1,%2,%3};"
        : "+f"(c[0]), "+f"(c[1]), "+f"(c[2]), "+f"(c[3])
        : "r"(a[0]), "r"(a[1]), "r"(a[2]), "r"(a[3]), "r"(b0), "r"(b1));
}

// ---- smem layout (bytes) — identical geometry to the 465us kernel ----
#define SM_BIAS 0
#define SM_TILE 1024
#define T_A     0                // 128 pix * 128B (hi64|lo64) = 16384
#define T_B     16384            // 128 oc  * 128B (hi64|lo64) = 16384
#define STG     32768
#define SMEM_TOTAL (SM_TILE + 3 * STG)   // 99328 -> 2 CTAs/SM

__global__ __launch_bounds__(NT, 2)
void conv_hmma_kernel(const float* __restrict__ bias, float* __restrict__ out) {
    extern __shared__ char smem[];
    const int tid  = threadIdx.x;
    const int lane = tid & 31;
    const int wid  = tid >> 5;
    const int m0   = blockIdx.x * BM;
    const int n0   = blockIdx.y * BN;

    ((float*)(smem + SM_BIAS))[tid] = bias[tid];   // NT == OC_

    // ---- A-producer: 4 pixels x one 16B chunk; 8 lanes cover one 128B line ----
    const int chA = tid & 7;
    const char* aptr[4];
    unsigned adst[4];
#pragma unroll
    for (int i = 0; i < 4; i++) {
        int pix  = (tid >> 3) + 32 * i;
        int p    = m0 + pix;
        int bimg = p / HW_;
        int hw   = p - bimg * HW_;
        int h    = hw / W_;
        int w    = hw - h * W_;
        aptr[i]  = (const char*)g_xhl
                 + (((size_t)bimg * HP + h) * WP + w) * 512 + chA * 16;
        adst[i]  = (unsigned)(pix * 128 + chA * 16);
    }

    auto load_stage = [&](int s, int slot) {
        char* stg = smem + SM_TILE + slot * STG;
        int tap = s >> 2;
        int cb  = s & 3;
        int kh  = tap / 3;
        int kw  = tap - 3 * kh;
        const size_t soff = ((size_t)kh * WP + kw) * 512 + (size_t)cb * 128;
        const unsigned abase_s = smem_u32(stg + T_A);
#pragma unroll
        for (int i = 0; i < 4; i++)
            cpa16(abase_s + sw128(adst[i]), aptr[i] + soff);
        // B: 8 lanes cover one oc's 128B stage block
#pragma unroll
        for (int i = 0; i < 4; i++) {
            int q  = tid + NT * i;
            int oc = q >> 3;
            int ch = q & 7;
            const char* bsrc = (const char*)g_whl
                             + (size_t)(n0 + oc) * 4608 + (tap * 4 + cb) * 128 + ch * 16;
            cpa16(smem_u32(stg + T_B + sw128((unsigned)(oc * 128 + ch * 16))), bsrc);
        }
        asm volatile("cp.async.commit_group;\n");
    };

    // warp tiling: 2 (M) x 4 (N) warps, warp tile 64 x 32
    const int wm = (wid & 1) * 64;
    const int wn = (wid >> 1) * 32;

    float acc[4][4][4];
#pragma unroll
    for (int a = 0; a < 4; a++)
#pragma unroll
        for (int b = 0; b < 4; b++)
#pragma unroll
            for (int cq = 0; cq < 4; cq++) acc[a][b][cq] = 0.0f;

    load_stage(0, 0);
    load_stage(1, 1);

    int slot = 0, slot2 = 2;
    for (int s = 0; s < NSTAGE; s++) {
        asm volatile("cp.async.wait_group 1;\n");
        __syncthreads();

        if (s + 2 < NSTAGE) load_stage(s + 2, slot2);
        else asm volatile("cp.async.commit_group;\n");

        char* stg = smem + SM_TILE + slot * STG;
        const unsigned abase = smem_u32(stg + T_A);
        const unsigned bbase = smem_u32(stg + T_B);

#pragma unroll
        for (int q = 0; q < 2; q++) {           // two 16-channel chunks
            unsigned Ah[4][4], Al[4][4];
#pragma unroll
            for (int mi = 0; mi < 4; mi++) {
                unsigned off = (unsigned)((wm + mi * 16 + (lane & 15)) * 128
                                          + q * 32 + (lane >> 4) * 16);
                ldsm4(Ah[mi], abase + sw128(off));        // hi bytes [0,64)
                ldsm4(Al[mi], abase + sw128(off + 64));   // lo bytes [64,128)
            }
#pragma unroll
            for (int ni = 0; ni < 2; ni++) {
                int g = lane >> 3, r = lane & 7;
                unsigned boff = (unsigned)((wn + ni * 16 + ((g & 2) ? 8 : 0) + r) * 128
                                           + q * 32 + (g & 1) * 16);
                unsigned Bh[4], Bl[4];
                ldsm4(Bh, bbase + sw128(boff));
                ldsm4(Bl, bbase + sw128(boff + 64));
                // T1: hi*hi
#pragma unroll
                for (int mi = 0; mi < 4; mi++)
                    mma16816(acc[mi][ni * 2 + 0], Ah[mi], Bh[0], Bh[1]);
#pragma unroll
                for (int mi = 0; mi < 4; mi++)
                    mma16816(acc[mi][ni * 2 + 1], Ah[mi], Bh[2], Bh[3]);
                // T2: lo*hi
#pragma unroll
                for (int mi = 0; mi < 4; mi++)
                    mma16816(acc[mi][ni * 2 + 0], Al[mi], Bh[0], Bh[1]);
#pragma unroll
                for (int mi = 0; mi < 4; mi++)
                    mma16816(acc[mi][ni * 2 + 1], Al[mi], Bh[2], Bh[3]);
                // T3: hi*lo
#pragma unroll
                for (int mi = 0; mi < 4; mi++)
                    mma16816(acc[mi][ni * 2 + 0], Ah[mi], Bl[0], Bl[1]);
#pragma unroll
                for (int mi = 0; mi < 4; mi++)
                    mma16816(acc[mi][ni * 2 + 1], Ah[mi], Bl[2], Bl[3]);
            }
        }

        slot  = (slot  == 2) ? 0 : slot  + 1;
        slot2 = (slot2 == 2) ? 0 : slot2 + 1;
    }

    __syncthreads();

    // ---- epilogue: transpose through smem, coalesced float4 stores ----
    float* Cs = (float*)(smem + SM_TILE);   // [oc 128][pix 128] = 64KB
#pragma unroll
    for (int mi = 0; mi < 4; mi++)
#pragma unroll
        for (int nq = 0; nq < 4; nq++) {
            int r0 = wm + mi * 16 + (lane >> 2);
            int cb = wn + nq * 8 + (lane & 3) * 2;
            Cs[(cb + 0) * BM + r0]     = acc[mi][nq][0];
            Cs[(cb + 1) * BM + r0]     = acc[mi][nq][1];
            Cs[(cb + 0) * BM + r0 + 8] = acc[mi][nq][2];
            Cs[(cb + 1) * BM + r0 + 8] = acc[mi][nq][3];
        }
    __syncthreads();

    const float* bs = (const float*)(smem + SM_BIAS);
    for (int g = tid; g < BN * (BM / 4); g += NT) {
        int ocl  = g >> 5;
        int pixl = (g & 31) * 4;
        int pp   = m0 + pixl;
        int bi   = pp / HW_;
        int off  = pp - bi * HW_;
        int oc   = n0 + ocl;
        float4 v = *(const float4*)&Cs[ocl * BM + pixl];
        float bv = bs[oc];
        v.x += bv; v.y += bv; v.z += bv; v.w += bv;
        *(float4*)(out + (size_t)bi * OC_ * HW_ + (size_t)oc * HW_ + off) = v;
    }
}

extern "C" void kernel_launch(void* const* d_in, const int* in_sizes, int n_in,
                              void* d_out, int out_size) {
    const float* x  = (const float*)d_in[0];
    const float* Wm = (const float*)d_in[1];
    const float* bb = (const float*)d_in[2];
    float* out      = (float*)d_out;

    dim3 pgrid(8, H_, B_ + 1);             // z = B_ slice does W split
    prep_kernel<<<pgrid, dim3(32, 8)>>>(x, Wm);

    cudaFuncSetAttribute(conv_hmma_kernel,
                         cudaFuncAttributeMaxDynamicSharedMemorySize, SMEM_TOTAL);
    dim3 grid(M_ / BM, OC_ / BN);   // 784 x 2
    conv_hmma_kernel<<<grid, NT, SMEM_TOTAL>>>(bb, out);
}